// round 14
// baseline (speedup 1.0000x reference)
#include <cuda_runtime.h>
#include <cuda_fp16.h>
#include <math.h>
#include <stdint.h>

#define D_MODEL 1024
#define SEQ     2048
#define BATCH   2
#define HEADS   16
#define HDIM    64
#define MROWS   (BATCH*SEQ)   // 4096

// GEMM tiling (fp16): 128x128 tile, K-chunk 64, pitch 72 halves (144B).
#define GP       72
#define GNIT     16
#define STG_H    (128*GP)         // halves per operand per stage (9216)
#define GSTG_B   (2*STG_H*2)      // bytes per stage (A+B) = 36864
#define GSMEM_B  (3*GSTG_B)       // 110592

// Attention: K/V tiles 64x64 fp16, pitch 72 halves. 4 stages, depth 3.
#define AP       72
#define KVH      (64*AP)          // 4608 halves per operand
#define ASTG_B   (2*KVH*2)        // 18432
#define FSMEM_B  GSMEM_B          // fused kernel smem = max(gemm, attn)

// Scratch (halves)
__device__ __half g_q[(size_t)MROWS * D_MODEL];
__device__ __half g_k[(size_t)MROWS * D_MODEL];
__device__ __half g_v[(size_t)MROWS * D_MODEL];
__device__ __half g_ctx[(size_t)MROWS * D_MODEL];
__device__ __half g_hx[(size_t)MROWS * D_MODEL];
__device__ __half g_hw[4 * (size_t)D_MODEL * D_MODEL];
__device__ unsigned g_cnt[BATCH * 16];   // per (b, 128-row q-tile) completion

// ---------------- PTX helpers ----------------
__device__ __forceinline__ uint32_t smem_u32(const void* p){
  uint32_t a;
  asm("{ .reg .u64 t; cvta.to.shared.u64 t, %1; cvt.u32.u64 %0, t; }" : "=r"(a) : "l"(p));
  return a;
}
__device__ __forceinline__ void cp_async16(uint32_t s, const void* g){
  asm volatile("cp.async.cg.shared.global [%0], [%1], 16;" :: "r"(s), "l"(g) : "memory");
}
__device__ __forceinline__ void cp_commit(){ asm volatile("cp.async.commit_group;" ::: "memory"); }
__device__ __forceinline__ void cp_wait0(){ asm volatile("cp.async.wait_group 0;" ::: "memory"); }
__device__ __forceinline__ void cp_wait1(){ asm volatile("cp.async.wait_group 1;" ::: "memory"); }
__device__ __forceinline__ void cp_wait2(){ asm volatile("cp.async.wait_group 2;" ::: "memory"); }
__device__ __forceinline__ void mma_f16(float* c, const uint32_t* a, const uint32_t* b){
  asm volatile(
    "mma.sync.aligned.m16n8k16.row.col.f32.f16.f16.f32 "
    "{%0,%1,%2,%3}, {%4,%5,%6,%7}, {%8,%9}, {%0,%1,%2,%3};"
    : "+f"(c[0]), "+f"(c[1]), "+f"(c[2]), "+f"(c[3])
    : "r"(a[0]), "r"(a[1]), "r"(a[2]), "r"(a[3]), "r"(b[0]), "r"(b[1]));
}
__device__ __forceinline__ void ldsm4(uint32_t* r, uint32_t addr){
  asm volatile("ldmatrix.sync.aligned.m8n8.x4.shared.b16 {%0,%1,%2,%3}, [%4];"
    : "=r"(r[0]), "=r"(r[1]), "=r"(r[2]), "=r"(r[3]) : "r"(addr));
}
__device__ __forceinline__ void ldsm4t(uint32_t* r, uint32_t addr){
  asm volatile("ldmatrix.sync.aligned.m8n8.x4.trans.shared.b16 {%0,%1,%2,%3}, [%4];"
    : "=r"(r[0]), "=r"(r[1]), "=r"(r[2]), "=r"(r[3]) : "r"(addr));
}
__device__ __forceinline__ uint32_t h2u(__half2 h){ return *(uint32_t*)&h; }

// ---------------------------------------------------------------------------
// Prep: convert X and all 4 weights to fp16; reset completion counters.
// ---------------------------------------------------------------------------
__global__ __launch_bounds__(256) void half_prep(
    const float4* __restrict__ X,
    const float4* __restrict__ Wq, const float4* __restrict__ Wk,
    const float4* __restrict__ Wv, const float4* __restrict__ Wo,
    __half2* __restrict__ hx, __half2* __restrict__ hw)
{
  if (blockIdx.x == 0 && threadIdx.x < BATCH*16) g_cnt[threadIdx.x] = 0u;
  const int XN = MROWS * D_MODEL / 4;
  const int WN = D_MODEL * D_MODEL / 4;
  const int total = XN + 4*WN;
  for (int i = blockIdx.x * 256 + threadIdx.x; i < total; i += gridDim.x * 256){
    const float4* src; __half2* dst; int j;
    if (i < XN){ src = X; dst = hx; j = i; }
    else {
      int w = (i - XN) / WN;
      j = (i - XN) - w*WN;
      src = (w == 0) ? Wq : (w == 1) ? Wk : (w == 2) ? Wv : Wo;
      dst = hw + (size_t)w * WN * 2;
    }
    float4 v = src[j];
    dst[2*j]   = __floats2half2_rn(v.x, v.y);
    dst[2*j+1] = __floats2half2_rn(v.z, v.w);
  }
}

// ---------------------------------------------------------------------------
// Shared gemm tile body (3-stage ring, depth 2). f32 out + bias when Cf!=0,
// else half out scaled by hscale.
// ---------------------------------------------------------------------------
static __device__ __forceinline__ void load_stage_g(
    uint32_t stBase, const __half* A, const __half* W,
    int m0, int n0, int k0, int tid)
{
#pragma unroll
  for (int u = 0; u < 4; u++){
    int q = tid + u*256;
    int r = q >> 3, c = q & 7;
    uint32_t so = (uint32_t)(r*GP + c*8) * 2u;
    cp_async16(stBase + so, A + (size_t)(m0 + r)*D_MODEL + k0 + c*8);
    cp_async16(stBase + (uint32_t)(STG_H*2) + so, W + (size_t)(n0 + r)*D_MODEL + k0 + c*8);
  }
}

static __device__ __forceinline__ void gemm_tile(
    const __half* __restrict__ A, const __half* __restrict__ W,
    float* __restrict__ Cf, __half* __restrict__ Ch,
    const float* __restrict__ bias, float hscale,
    int m0, int n0, uint32_t sb, int tid)
{
  const int wid  = tid >> 5;
  const int lane = tid & 31;
  const int g    = lane >> 2;
  const int t4   = lane & 3;
  const int wm   = wid >> 2;
  const int wn   = wid & 3;

  uint32_t a_off[4], b_off[2];
  {
    const int ra = (lane & 7) + ((lane >> 3) & 1) * 8;
    const int ka = ((lane >> 4) & 1) * 8;
    const int rb = (lane & 7) + ((lane >> 4) & 1) * 8;
    const int kb = ((lane >> 3) & 1) * 8;
#pragma unroll
    for (int mt = 0; mt < 4; mt++)
      a_off[mt] = (uint32_t)(((wm*64 + mt*16 + ra)*GP + ka) * 2);
#pragma unroll
    for (int np = 0; np < 2; np++)
      b_off[np] = (uint32_t)(((wn*32 + np*16 + rb)*GP + kb) * 2) + (uint32_t)(STG_H*2);
  }

  float c[4][4][4];
#pragma unroll
  for (int i = 0; i < 4; i++)
#pragma unroll
    for (int j = 0; j < 4; j++)
#pragma unroll
      for (int r = 0; r < 4; r++) c[i][j][r] = 0.0f;

#pragma unroll
  for (int p = 0; p < 2; p++){
    load_stage_g(sb + (uint32_t)p*GSTG_B, A, W, m0, n0, p*64, tid);
    cp_commit();
  }

  int stage = 0;
  for (int it = 0; it < GNIT; it++){
    cp_wait1();
    __syncthreads();
    if (it + 2 < GNIT){
      int sn = stage + 2; if (sn >= 3) sn -= 3;
      load_stage_g(sb + (uint32_t)sn*GSTG_B, A, W, m0, n0, (it+2)*64, tid);
    }
    cp_commit();
    const uint32_t stBase = sb + (uint32_t)stage*GSTG_B;
#pragma unroll
    for (int ks = 0; ks < 4; ks++){
      const uint32_t kbyte = (uint32_t)(ks*32);
      uint32_t af[4][4], bf[2][4];
#pragma unroll
      for (int mt = 0; mt < 4; mt++) ldsm4(af[mt], stBase + a_off[mt] + kbyte);
#pragma unroll
      for (int np = 0; np < 2; np++) ldsm4(bf[np], stBase + b_off[np] + kbyte);
#pragma unroll
      for (int mt = 0; mt < 4; mt++)
#pragma unroll
        for (int nt = 0; nt < 4; nt++)
          mma_f16(c[mt][nt], af[mt], &bf[nt >> 1][(nt & 1)*2]);
    }
    if (++stage == 3) stage = 0;
  }

  if (Cf){
#pragma unroll
    for (int mt = 0; mt < 4; mt++){
      const int r0 = m0 + wm*64 + mt*16 + g;
#pragma unroll
      for (int nt = 0; nt < 4; nt++){
        const int col = n0 + wn*32 + nt*8 + t4*2;
        float b0 = bias ? bias[col] : 0.0f, b1 = bias ? bias[col+1] : 0.0f;
        *(float2*)&Cf[(size_t)r0*D_MODEL + col]     = make_float2(c[mt][nt][0]+b0, c[mt][nt][1]+b1);
        *(float2*)&Cf[(size_t)(r0+8)*D_MODEL + col] = make_float2(c[mt][nt][2]+b0, c[mt][nt][3]+b1);
      }
    }
  } else {
#pragma unroll
    for (int mt = 0; mt < 4; mt++){
      const int r0 = m0 + wm*64 + mt*16 + g;
#pragma unroll
      for (int nt = 0; nt < 4; nt++){
        const int col = n0 + wn*32 + nt*8 + t4*2;
        *(__half2*)(Ch + (size_t)r0*D_MODEL + col)     = __floats2half2_rn(c[mt][nt][0]*hscale, c[mt][nt][1]*hscale);
        *(__half2*)(Ch + (size_t)(r0+8)*D_MODEL + col) = __floats2half2_rn(c[mt][nt][2]*hscale, c[mt][nt][3]*hscale);
      }
    }
  }
}

// ---------------------------------------------------------------------------
// QKV gemm kernel (half out; z==0 scaled by 1/64).
// ---------------------------------------------------------------------------
__global__ __launch_bounds__(256) void gemm_h(
    const __half* __restrict__ A,
    const __half* __restrict__ Wa, const __half* __restrict__ Wb, const __half* __restrict__ Wc,
    __half* __restrict__ Ca, __half* __restrict__ Cb, __half* __restrict__ Cc)
{
  const __half* W = (blockIdx.z == 0) ? Wa : (blockIdx.z == 1) ? Wb : Wc;
  __half*       C = (blockIdx.z == 0) ? Ca : (blockIdx.z == 1) ? Cb : Cc;
  extern __shared__ __half smh[];
  gemm_tile(A, W, nullptr, C, nullptr,
            (blockIdx.z == 0) ? 0.015625f : 1.0f,
            blockIdx.y * 128, blockIdx.x * 128, smem_u32(smh), threadIdx.x);
}

// ---------------------------------------------------------------------------
// Fused attention + Wo-gemm kernel.
// y<32: attention for bh=y. y in [32,48): Wo gemm tiles (spin on counters).
// ---------------------------------------------------------------------------
static __device__ __forceinline__ void load_kv(
    uint32_t sb, int stage, const __half* Kt, const __half* Vt, int tid)
{
  const uint32_t base = sb + (uint32_t)stage * ASTG_B;
#pragma unroll
  for (int u = 0; u < 2; u++){
    int idx = tid + u*256;
    int r = idx >> 3, c = idx & 7;
    uint32_t so = (uint32_t)(r*AP + c*8) * 2u;
    cp_async16(base + so, Kt + (size_t)r*HDIM + c*8);
    cp_async16(base + (uint32_t)(KVH*2) + so, Vt + (size_t)r*HDIM + c*8);
  }
}

__global__ __launch_bounds__(256) void attn_wo(
    const __half* __restrict__ Qg, const __half* __restrict__ Kg,
    const __half* __restrict__ Vg, __half* __restrict__ ctx,
    const __half* __restrict__ hWo, const float* __restrict__ bo,
    float* __restrict__ out)
{
  extern __shared__ __half smh[];
  const uint32_t sb = smem_u32(smh);
  const int tid = threadIdx.x;

  if (blockIdx.y >= BATCH*HEADS){
    // ---- Wo gemm tile (consumer) ----
    const int t  = ((int)blockIdx.y - BATCH*HEADS) * 16 + (int)blockIdx.x;  // 0..255
    const int n0 = (t >> 5) * 128;
    const int m0 = (t & 31) * 128;
    const unsigned idx = (unsigned)((m0 >> 11) * 16 + ((m0 & 2047) >> 7));
    if (tid == 0){
      while (atomicAdd(&g_cnt[idx], 0u) < (unsigned)HEADS) __nanosleep(128);
    }
    __syncthreads();
    gemm_tile(ctx, hWo, out, nullptr, bo, 1.0f, m0, n0, sb, tid);
    return;
  }

  // ---- attention (producer) ----
  const int wid  = tid >> 5;
  const int lane = tid & 31;
  const int g    = lane >> 2;
  const int t4   = lane & 3;
  const int bh   = blockIdx.y;
  const int qt   = (int)gridDim.x - 1 - (int)blockIdx.x;   // heavy first
  const int qbase = qt * 128;

  const __half* Qh = Qg + (size_t)bh * SEQ * HDIM;
  const __half* Kh = Kg + (size_t)bh * SEQ * HDIM;
  const __half* Vh = Vg + (size_t)bh * SEQ * HDIM;

  uint32_t q_off, k_off[4], v_off;
  {
    const int ra = (lane & 7) + ((lane >> 3) & 1) * 8;
    const int ka = ((lane >> 4) & 1) * 8;
    q_off = (uint32_t)(((wid*16 + ra)*AP + ka) * 2);
    const int rb = (lane & 7) + ((lane >> 4) & 1) * 8;
    const int kb = ((lane >> 3) & 1) * 8;
#pragma unroll
    for (int np = 0; np < 4; np++)
      k_off[np] = (uint32_t)(((np*16 + rb)*AP + kb) * 2);
    const int kr = (lane & 7) + ((lane >> 3) & 1) * 8;
    const int nc = ((lane >> 4) & 1) * 8;
    v_off = (uint32_t)((kr*AP + nc) * 2) + (uint32_t)(KVH*2);
  }

#pragma unroll
  for (int u = 0; u < 4; u++){
    int idx = tid + u*256;
    int r = idx >> 3, c = idx & 7;
    cp_async16(sb + (uint32_t)(r*AP + c*8)*2u, Qh + (size_t)(qbase + r)*HDIM + c*8);
  }
  cp_commit();
  cp_wait0();
  __syncthreads();

  uint32_t qa[4][4];
#pragma unroll
  for (int ks = 0; ks < 4; ks++) ldsm4(qa[ks], sb + q_off + (uint32_t)(ks*32));
  __syncthreads();

  float oc[8][4];
#pragma unroll
  for (int nb = 0; nb < 8; nb++)
#pragma unroll
    for (int r = 0; r < 4; r++) oc[nb][r] = 0.0f;
  float m0s = -1e30f, m1s = -1e30f, l0 = 0.0f, l1 = 0.0f;

  const int nkt = 2*qt + 2;

#pragma unroll
  for (int p = 0; p < 3; p++){
    if (p < nkt) load_kv(sb, p, Kh + (size_t)p*64*HDIM, Vh + (size_t)p*64*HDIM, tid);
    cp_commit();
  }

  const int grow0 = qbase + wid*16 + g;
  const int grow1 = grow0 + 8;

  for (int ki = 0; ki < nkt; ki++){
    cp_wait2();
    __syncthreads();
    if (ki + 3 < nkt)
      load_kv(sb, (ki+3) & 3, Kh + (size_t)(ki+3)*64*HDIM, Vh + (size_t)(ki+3)*64*HDIM, tid);
    cp_commit();

    if (ki == 2*qt + 1 && wid < 4) continue;

    const uint32_t kBase = sb + (uint32_t)(ki & 3)*ASTG_B;

    float sc[8][4];
#pragma unroll
    for (int nb = 0; nb < 8; nb++)
#pragma unroll
      for (int r = 0; r < 4; r++) sc[nb][r] = 0.0f;
#pragma unroll
    for (int ks = 0; ks < 4; ks++){
      const uint32_t kbyte = (uint32_t)(ks*32);
#pragma unroll
      for (int np = 0; np < 4; np++){
        uint32_t kf[4];
        ldsm4(kf, kBase + k_off[np] + kbyte);
        mma_f16(sc[2*np],   qa[ks], &kf[0]);
        mma_f16(sc[2*np+1], qa[ks], &kf[2]);
      }
    }

    if (ki >= 2*qt){
      const int cb = ki*64 + 2*t4;
#pragma unroll
      for (int nb = 0; nb < 8; nb++){
        const int c0 = cb + 8*nb, c1 = c0 + 1;
        if (c0 > grow0) sc[nb][0] = -1e30f;
        if (c1 > grow0) sc[nb][1] = -1e30f;
        if (c0 > grow1) sc[nb][2] = -1e30f;
        if (c1 > grow1) sc[nb][3] = -1e30f;
      }
    }

    float mx0 = -1e30f, mx1 = -1e30f;
#pragma unroll
    for (int nb = 0; nb < 8; nb++){
      mx0 = fmaxf(mx0, fmaxf(sc[nb][0], sc[nb][1]));
      mx1 = fmaxf(mx1, fmaxf(sc[nb][2], sc[nb][3]));
    }
    mx0 = fmaxf(mx0, __shfl_xor_sync(0xffffffffu, mx0, 1));
    mx0 = fmaxf(mx0, __shfl_xor_sync(0xffffffffu, mx0, 2));
    mx1 = fmaxf(mx1, __shfl_xor_sync(0xffffffffu, mx1, 1));
    mx1 = fmaxf(mx1, __shfl_xor_sync(0xffffffffu, mx1, 2));
    const float mn0 = fmaxf(m0s, mx0), mn1 = fmaxf(m1s, mx1);
    const float al0 = __expf(m0s - mn0), al1 = __expf(m1s - mn1);
    m0s = mn0; m1s = mn1;

    uint32_t ph[8][2];
    float sum0 = 0.0f, sum1 = 0.0f;
#pragma unroll
    for (int nb = 0; nb < 8; nb++){
      float p0 = __expf(sc[nb][0] - mn0);
      float p1 = __expf(sc[nb][1] - mn0);
      float p2 = __expf(sc[nb][2] - mn1);
      float p3 = __expf(sc[nb][3] - mn1);
      sum0 += p0 + p1; sum1 += p2 + p3;
      ph[nb][0] = h2u(__floats2half2_rn(p0, p1));
      ph[nb][1] = h2u(__floats2half2_rn(p2, p3));
    }
    sum0 += __shfl_xor_sync(0xffffffffu, sum0, 1);
    sum0 += __shfl_xor_sync(0xffffffffu, sum0, 2);
    sum1 += __shfl_xor_sync(0xffffffffu, sum1, 1);
    sum1 += __shfl_xor_sync(0xffffffffu, sum1, 2);
    l0 = l0*al0 + sum0; l1 = l1*al1 + sum1;

    if (!__all_sync(0xffffffffu, (al0 == 1.0f) && (al1 == 1.0f))){
#pragma unroll
      for (int nb = 0; nb < 8; nb++){
        oc[nb][0] *= al0; oc[nb][1] *= al0;
        oc[nb][2] *= al1; oc[nb][3] *= al1;
      }
    }

#pragma unroll
    for (int ks = 0; ks < 4; ks++){
      uint32_t a[4];
      a[0] = ph[2*ks][0];   a[1] = ph[2*ks][1];
      a[2] = ph[2*ks+1][0]; a[3] = ph[2*ks+1][1];
      const uint32_t vrow = (uint32_t)(ks*16*AP*2);
#pragma unroll
      for (int nb16 = 0; nb16 < 4; nb16++){
        uint32_t vf[4];
        ldsm4t(vf, kBase + v_off + vrow + (uint32_t)(nb16*32));
        mma_f16(oc[2*nb16],   a, &vf[0]);
        mma_f16(oc[2*nb16+1], a, &vf[2]);
      }
    }
  }

  // ---- epilogue: normalize, write ctx half, signal completion ----
  const int b = bh >> 4, h = bh & 15;
  const float inv0 = 1.0f / l0, inv1 = 1.0f / l1;
  __half* base0 = ctx + ((size_t)(b*SEQ + grow0)) * D_MODEL + h*HDIM;
#pragma unroll
  for (int nb = 0; nb < 8; nb++){
    const int col = 8*nb + 2*t4;
    *(__half2*)(base0 + col) = __floats2half2_rn(oc[nb][0]*inv0, oc[nb][1]*inv0);
    *(__half2*)(base0 + 8*(size_t)D_MODEL + col) = __floats2half2_rn(oc[nb][2]*inv1, oc[nb][3]*inv1);
  }
  __threadfence();
  __syncthreads();
  if (tid == 0) atomicAdd(&g_cnt[b*16 + qt], 1u);
}

// ---------------------------------------------------------------------------
extern "C" void kernel_launch(void* const* d_in, const int* in_sizes, int n_in,
                              void* d_out, int out_size)
{
    const float* X  = (const float*)d_in[0];
    const float* Wq = (const float*)d_in[1];
    const float* Wk = (const float*)d_in[2];
    const float* Wv = (const float*)d_in[3];
    const float* Wo = (const float*)d_in[4];
    const float* bo = (const float*)d_in[5];
    float* out = (float*)d_out;

    __half *pq, *pk, *pv, *pctx, *phx, *phw;
    cudaGetSymbolAddress((void**)&pq,  g_q);
    cudaGetSymbolAddress((void**)&pk,  g_k);
    cudaGetSymbolAddress((void**)&pv,  g_v);
    cudaGetSymbolAddress((void**)&pctx, g_ctx);
    cudaGetSymbolAddress((void**)&phx, g_hx);
    cudaGetSymbolAddress((void**)&phw, g_hw);

    const size_t WSZ = (size_t)D_MODEL * D_MODEL;
    const __half* hWq = phw;
    const __half* hWk = phw + WSZ;
    const __half* hWv = phw + 2*WSZ;
    const __half* hWo = phw + 3*WSZ;

    // Convert X + all 4 weights; reset completion counters.
    half_prep<<<592, 256>>>((const float4*)X, (const float4*)Wq, (const float4*)Wk,
                            (const float4*)Wv, (const float4*)Wo,
                            (__half2*)phx, (__half2*)phw);

    cudaFuncSetAttribute(gemm_h, cudaFuncAttributeMaxDynamicSharedMemorySize, GSMEM_B);
    gemm_h<<<dim3(8, 32, 3), 256, GSMEM_B>>>(phx, hWq, hWk, hWv, pq, pk, pv);

    cudaFuncSetAttribute(attn_wo, cudaFuncAttributeMaxDynamicSharedMemorySize, FSMEM_B);
    // y<32: attention; y in [32,48): 256 Wo-gemm tiles riding the tail.
    attn_wo<<<dim3(SEQ/128, BATCH*HEADS + 16), 256, FSMEM_B>>>(
        pq, pk, pv, pctx, hWo, bo, out);
}

// round 16
// speedup vs baseline: 1.0267x; 1.0267x over previous
#include <cuda_runtime.h>
#include <cuda_fp16.h>
#include <math.h>
#include <stdint.h>

#define D_MODEL 1024
#define SEQ     2048
#define BATCH   2
#define HEADS   16
#define HDIM    64
#define MROWS   (BATCH*SEQ)   // 4096

// GEMM tiling (fp16): 128x128 tile, K-chunk 64, pitch 72 halves (144B).
// 3 smem stages, prefetch depth 2.
#define GP       72
#define GNIT     16
#define STG_H    (128*GP)         // halves per operand per stage (9216)
#define GSTG_B   (2*STG_H*2)      // bytes per stage (A+B) = 36864
#define GSMEM_B  (3*GSTG_B)       // 110592

// Attention: K/V tiles 64x64 fp16, pitch 72 halves. 4 stages, depth 3.
#define AP       72
#define KVH      (64*AP)          // 4608 halves per operand
#define ASTG_B   (2*KVH*2)        // bytes per stage (K+V) = 18432
#define ASMEM_B  (4*ASTG_B)       // 73728

// Scratch (halves)
__device__ __half g_q[(size_t)MROWS * D_MODEL];
__device__ __half g_k[(size_t)MROWS * D_MODEL];
__device__ __half g_v[(size_t)MROWS * D_MODEL];
__device__ __half g_ctx[(size_t)MROWS * D_MODEL];
__device__ __half g_hx[(size_t)MROWS * D_MODEL];
__device__ __half g_hw[4 * (size_t)D_MODEL * D_MODEL];

// ---------------- PTX helpers ----------------
__device__ __forceinline__ uint32_t smem_u32(const void* p){
  uint32_t a;
  asm("{ .reg .u64 t; cvta.to.shared.u64 t, %1; cvt.u32.u64 %0, t; }" : "=r"(a) : "l"(p));
  return a;
}
__device__ __forceinline__ void cp_async16(uint32_t s, const void* g){
  asm volatile("cp.async.cg.shared.global [%0], [%1], 16;" :: "r"(s), "l"(g) : "memory");
}
__device__ __forceinline__ void cp_commit(){ asm volatile("cp.async.commit_group;" ::: "memory"); }
__device__ __forceinline__ void cp_wait0(){ asm volatile("cp.async.wait_group 0;" ::: "memory"); }
__device__ __forceinline__ void cp_wait1(){ asm volatile("cp.async.wait_group 1;" ::: "memory"); }
__device__ __forceinline__ void cp_wait2(){ asm volatile("cp.async.wait_group 2;" ::: "memory"); }
__device__ __forceinline__ void mma_f16(float* c, const uint32_t* a, const uint32_t* b){
  asm volatile(
    "mma.sync.aligned.m16n8k16.row.col.f32.f16.f16.f32 "
    "{%0,%1,%2,%3}, {%4,%5,%6,%7}, {%8,%9}, {%0,%1,%2,%3};"
    : "+f"(c[0]), "+f"(c[1]), "+f"(c[2]), "+f"(c[3])
    : "r"(a[0]), "r"(a[1]), "r"(a[2]), "r"(a[3]), "r"(b[0]), "r"(b[1]));
}
__device__ __forceinline__ void ldsm4(uint32_t* r, uint32_t addr){
  asm volatile("ldmatrix.sync.aligned.m8n8.x4.shared.b16 {%0,%1,%2,%3}, [%4];"
    : "=r"(r[0]), "=r"(r[1]), "=r"(r[2]), "=r"(r[3]) : "r"(addr));
}
__device__ __forceinline__ void ldsm4t(uint32_t* r, uint32_t addr){
  asm volatile("ldmatrix.sync.aligned.m8n8.x4.trans.shared.b16 {%0,%1,%2,%3}, [%4];"
    : "=r"(r[0]), "=r"(r[1]), "=r"(r[2]), "=r"(r[3]) : "r"(addr));
}
__device__ __forceinline__ uint32_t h2u(__half2 h){ return *(uint32_t*)&h; }

// ---------------------------------------------------------------------------
// Prep: convert X and Wq/Wk/Wv to fp16. (Wo conversion deferred into attn tail.)
// ---------------------------------------------------------------------------
__global__ __launch_bounds__(256) void half_prep(
    const float4* __restrict__ X,
    const float4* __restrict__ Wq, const float4* __restrict__ Wk,
    const float4* __restrict__ Wv,
    __half2* __restrict__ hx, __half2* __restrict__ hw)
{
  const int XN = MROWS * D_MODEL / 4;
  const int WN = D_MODEL * D_MODEL / 4;
  const int total = XN + 3*WN;
  for (int i = blockIdx.x * 256 + threadIdx.x; i < total; i += gridDim.x * 256){
    const float4* src; __half2* dst; int j;
    if (i < XN){ src = X; dst = hx; j = i; }
    else {
      int w = (i - XN) / WN;
      j = (i - XN) - w*WN;
      src = (w == 0) ? Wq : (w == 1) ? Wk : Wv;
      dst = hw + (size_t)w * WN * 2;
    }
    float4 v = src[j];
    dst[2*j]   = __floats2half2_rn(v.x, v.y);
    dst[2*j+1] = __floats2half2_rn(v.z, v.w);
  }
}

// ---------------------------------------------------------------------------
// fp16 mma GEMM, 3-stage cp.async ring (prefetch depth 2).
// mode 0: f32 out + bias. mode 1: half out; z==0 scaled by 1/64.
// ---------------------------------------------------------------------------
static __device__ __forceinline__ void load_stage_g(
    uint32_t stBase, const __half* A, const __half* W,
    int m0, int n0, int k0, int tid)
{
#pragma unroll
  for (int u = 0; u < 4; u++){
    int q = tid + u*256;          // 0..1023 chunks (8 halves = 16B)
    int r = q >> 3, c = q & 7;
    uint32_t so = (uint32_t)(r*GP + c*8) * 2u;
    cp_async16(stBase + so, A + (size_t)(m0 + r)*D_MODEL + k0 + c*8);
    cp_async16(stBase + (uint32_t)(STG_H*2) + so, W + (size_t)(n0 + r)*D_MODEL + k0 + c*8);
  }
}

__global__ __launch_bounds__(256) void gemm_h(
    const __half* __restrict__ A,
    const __half* __restrict__ Wa, const __half* __restrict__ Wb, const __half* __restrict__ Wc,
    void* __restrict__ Ca, void* __restrict__ Cb, void* __restrict__ Cc,
    const float* __restrict__ bias, int mode)
{
  const __half* W = (blockIdx.z == 0) ? Wa : (blockIdx.z == 1) ? Wb : Wc;
  void*         C = (blockIdx.z == 0) ? Ca : (blockIdx.z == 1) ? Cb : Cc;

  extern __shared__ __half smh[];
  const uint32_t sb = smem_u32(smh);

  const int tid  = threadIdx.x;
  const int wid  = tid >> 5;
  const int lane = tid & 31;
  const int g    = lane >> 2;
  const int t4   = lane & 3;
  const int wm   = wid >> 2;
  const int wn   = wid & 3;
  const int m0   = blockIdx.y * 128;
  const int n0   = blockIdx.x * 128;

  uint32_t a_off[4], b_off[2];
  {
    const int ra = (lane & 7) + ((lane >> 3) & 1) * 8;
    const int ka = ((lane >> 4) & 1) * 8;
    const int rb = (lane & 7) + ((lane >> 4) & 1) * 8;
    const int kb = ((lane >> 3) & 1) * 8;
#pragma unroll
    for (int mt = 0; mt < 4; mt++)
      a_off[mt] = (uint32_t)(((wm*64 + mt*16 + ra)*GP + ka) * 2);
#pragma unroll
    for (int np = 0; np < 2; np++)
      b_off[np] = (uint32_t)(((wn*32 + np*16 + rb)*GP + kb) * 2) + (uint32_t)(STG_H*2);
  }

  float c[4][4][4];
#pragma unroll
  for (int i = 0; i < 4; i++)
#pragma unroll
    for (int j = 0; j < 4; j++)
#pragma unroll
      for (int r = 0; r < 4; r++) c[i][j][r] = 0.0f;

#pragma unroll
  for (int p = 0; p < 2; p++){
    load_stage_g(sb + (uint32_t)p*GSTG_B, A, W, m0, n0, p*64, tid);
    cp_commit();
  }

  int stage = 0;
  for (int it = 0; it < GNIT; it++){
    cp_wait1();
    __syncthreads();
    if (it + 2 < GNIT){
      int sn = stage + 2; if (sn >= 3) sn -= 3;
      load_stage_g(sb + (uint32_t)sn*GSTG_B, A, W, m0, n0, (it+2)*64, tid);
    }
    cp_commit();
    const uint32_t stBase = sb + (uint32_t)stage*GSTG_B;
#pragma unroll
    for (int ks = 0; ks < 4; ks++){
      const uint32_t kbyte = (uint32_t)(ks*32);
      uint32_t af[4][4], bf[2][4];
#pragma unroll
      for (int mt = 0; mt < 4; mt++) ldsm4(af[mt], stBase + a_off[mt] + kbyte);
#pragma unroll
      for (int np = 0; np < 2; np++) ldsm4(bf[np], stBase + b_off[np] + kbyte);
#pragma unroll
      for (int mt = 0; mt < 4; mt++)
#pragma unroll
        for (int nt = 0; nt < 4; nt++)
          mma_f16(c[mt][nt], af[mt], &bf[nt >> 1][(nt & 1)*2]);
    }
    if (++stage == 3) stage = 0;
  }

  if (mode == 1){
    const float s = (blockIdx.z == 0) ? 0.015625f : 1.0f;
    __half* Ch = (__half*)C;
#pragma unroll
    for (int mt = 0; mt < 4; mt++){
      const int r0 = m0 + wm*64 + mt*16 + g;
#pragma unroll
      for (int nt = 0; nt < 4; nt++){
        const int col = n0 + wn*32 + nt*8 + t4*2;
        *(__half2*)(Ch + (size_t)r0*D_MODEL + col)     = __floats2half2_rn(c[mt][nt][0]*s, c[mt][nt][1]*s);
        *(__half2*)(Ch + (size_t)(r0+8)*D_MODEL + col) = __floats2half2_rn(c[mt][nt][2]*s, c[mt][nt][3]*s);
      }
    }
  } else {
    float* Cf = (float*)C;
#pragma unroll
    for (int mt = 0; mt < 4; mt++){
      const int r0 = m0 + wm*64 + mt*16 + g;
#pragma unroll
      for (int nt = 0; nt < 4; nt++){
        const int col = n0 + wn*32 + nt*8 + t4*2;
        float b0 = bias ? bias[col] : 0.0f, b1 = bias ? bias[col+1] : 0.0f;
        *(float2*)&Cf[(size_t)r0*D_MODEL + col]     = make_float2(c[mt][nt][0]+b0, c[mt][nt][1]+b1);
        *(float2*)&Cf[(size_t)(r0+8)*D_MODEL + col] = make_float2(c[mt][nt][2]+b0, c[mt][nt][3]+b1);
      }
    }
  }
}

// ---------------------------------------------------------------------------
// fp16 mma flash attention, 4-stage K/V ring (depth 3).
// Grid y: 0..31 = (b,h) attention; y==32 = Wo fp32->fp16 conversion CTAs
// (dependency-free tail-riders, launch last by CTA linearization).
// Warps 0-3 skip compute on the final k-tile (fully masked for their rows).
// Warp-voted alpha==1 skip on the oc rescale (bit-exact: x*1.0 identity).
// ---------------------------------------------------------------------------
static __device__ __forceinline__ void load_kv(
    uint32_t sb, int stage, const __half* Kt, const __half* Vt, int tid)
{
  const uint32_t base = sb + (uint32_t)stage * ASTG_B;
#pragma unroll
  for (int u = 0; u < 2; u++){
    int idx = tid + u*256;
    int r = idx >> 3, c = idx & 7;
    uint32_t so = (uint32_t)(r*AP + c*8) * 2u;
    cp_async16(base + so, Kt + (size_t)r*HDIM + c*8);
    cp_async16(base + (uint32_t)(KVH*2) + so, Vt + (size_t)r*HDIM + c*8);
  }
}

__global__ __launch_bounds__(256) void attn_h(
    const __half* __restrict__ Qg, const __half* __restrict__ Kg,
    const __half* __restrict__ Vg, __half* __restrict__ ctx,
    const float4* __restrict__ WoSrc, __half2* __restrict__ hWoDst)
{
  const int tid  = threadIdx.x;

  // Tail-rider CTAs: convert Wo to fp16 (needed only by the NEXT kernel).
  if (blockIdx.y >= BATCH*HEADS){
    const int WN = D_MODEL * D_MODEL / 4;   // float4 count
    for (int i = (int)blockIdx.x * 256 + tid; i < WN; i += 16*256){
      float4 v = WoSrc[i];
      hWoDst[2*i]   = __floats2half2_rn(v.x, v.y);
      hWoDst[2*i+1] = __floats2half2_rn(v.z, v.w);
    }
    return;
  }

  extern __shared__ __half smh[];
  const uint32_t sb = smem_u32(smh);

  const int wid  = tid >> 5;
  const int lane = tid & 31;
  const int g    = lane >> 2;
  const int t4   = lane & 3;
  const int bh   = blockIdx.y;
  const int qt   = (int)gridDim.x - 1 - (int)blockIdx.x;   // heavy first
  const int qbase = qt * 128;

  const __half* Qh = Qg + (size_t)bh * SEQ * HDIM;
  const __half* Kh = Kg + (size_t)bh * SEQ * HDIM;
  const __half* Vh = Vg + (size_t)bh * SEQ * HDIM;

  uint32_t q_off, k_off[4], v_off;
  {
    const int ra = (lane & 7) + ((lane >> 3) & 1) * 8;
    const int ka = ((lane >> 4) & 1) * 8;
    q_off = (uint32_t)(((wid*16 + ra)*AP + ka) * 2);
    const int rb = (lane & 7) + ((lane >> 4) & 1) * 8;
    const int kb = ((lane >> 3) & 1) * 8;
#pragma unroll
    for (int np = 0; np < 4; np++)
      k_off[np] = (uint32_t)(((np*16 + rb)*AP + kb) * 2);
    const int kr = (lane & 7) + ((lane >> 3) & 1) * 8;
    const int nc = ((lane >> 4) & 1) * 8;
    v_off = (uint32_t)((kr*AP + nc) * 2) + (uint32_t)(KVH*2);
  }

#pragma unroll
  for (int u = 0; u < 4; u++){
    int idx = tid + u*256;
    int r = idx >> 3, c = idx & 7;
    cp_async16(sb + (uint32_t)(r*AP + c*8)*2u, Qh + (size_t)(qbase + r)*HDIM + c*8);
  }
  cp_commit();
  cp_wait0();
  __syncthreads();

  uint32_t qa[4][4];
#pragma unroll
  for (int ks = 0; ks < 4; ks++) ldsm4(qa[ks], sb + q_off + (uint32_t)(ks*32));
  __syncthreads();

  float oc[8][4];
#pragma unroll
  for (int nb = 0; nb < 8; nb++)
#pragma unroll
    for (int r = 0; r < 4; r++) oc[nb][r] = 0.0f;
  float m0 = -1e30f, m1 = -1e30f, l0 = 0.0f, l1 = 0.0f;

  const int nkt = 2*qt + 2;

#pragma unroll
  for (int p = 0; p < 3; p++){
    if (p < nkt) load_kv(sb, p, Kh + (size_t)p*64*HDIM, Vh + (size_t)p*64*HDIM, tid);
    cp_commit();
  }

  const int grow0 = qbase + wid*16 + g;
  const int grow1 = grow0 + 8;

  for (int ki = 0; ki < nkt; ki++){
    cp_wait2();
    __syncthreads();
    if (ki + 3 < nkt)
      load_kv(sb, (ki+3) & 3, Kh + (size_t)(ki+3)*64*HDIM, Vh + (size_t)(ki+3)*64*HDIM, tid);
    cp_commit();

    if (ki == 2*qt + 1 && wid < 4) continue;

    const uint32_t kBase = sb + (uint32_t)(ki & 3)*ASTG_B;

    // ---- S = Q @ K^T ----
    float sc[8][4];
#pragma unroll
    for (int nb = 0; nb < 8; nb++)
#pragma unroll
      for (int r = 0; r < 4; r++) sc[nb][r] = 0.0f;
#pragma unroll
    for (int ks = 0; ks < 4; ks++){
      const uint32_t kbyte = (uint32_t)(ks*32);
#pragma unroll
      for (int np = 0; np < 4; np++){
        uint32_t kf[4];
        ldsm4(kf, kBase + k_off[np] + kbyte);
        mma_f16(sc[2*np],   qa[ks], &kf[0]);
        mma_f16(sc[2*np+1], qa[ks], &kf[2]);
      }
    }

    // ---- causal mask ----
    if (ki >= 2*qt){
      const int cb = ki*64 + 2*t4;
#pragma unroll
      for (int nb = 0; nb < 8; nb++){
        const int c0 = cb + 8*nb, c1 = c0 + 1;
        if (c0 > grow0) sc[nb][0] = -1e30f;
        if (c1 > grow0) sc[nb][1] = -1e30f;
        if (c0 > grow1) sc[nb][2] = -1e30f;
        if (c1 > grow1) sc[nb][3] = -1e30f;
      }
    }

    // ---- online softmax (rows quad-local) ----
    float mx0 = -1e30f, mx1 = -1e30f;
#pragma unroll
    for (int nb = 0; nb < 8; nb++){
      mx0 = fmaxf(mx0, fmaxf(sc[nb][0], sc[nb][1]));
      mx1 = fmaxf(mx1, fmaxf(sc[nb][2], sc[nb][3]));
    }
    mx0 = fmaxf(mx0, __shfl_xor_sync(0xffffffffu, mx0, 1));
    mx0 = fmaxf(mx0, __shfl_xor_sync(0xffffffffu, mx0, 2));
    mx1 = fmaxf(mx1, __shfl_xor_sync(0xffffffffu, mx1, 1));
    mx1 = fmaxf(mx1, __shfl_xor_sync(0xffffffffu, mx1, 2));
    const float mn0 = fmaxf(m0, mx0), mn1 = fmaxf(m1, mx1);
    const float al0 = __expf(m0 - mn0), al1 = __expf(m1 - mn1);
    m0 = mn0; m1 = mn1;

    uint32_t ph[8][2];
    float sum0 = 0.0f, sum1 = 0.0f;
#pragma unroll
    for (int nb = 0; nb < 8; nb++){
      float p0 = __expf(sc[nb][0] - mn0);
      float p1 = __expf(sc[nb][1] - mn0);
      float p2 = __expf(sc[nb][2] - mn1);
      float p3 = __expf(sc[nb][3] - mn1);
      sum0 += p0 + p1; sum1 += p2 + p3;
      ph[nb][0] = h2u(__floats2half2_rn(p0, p1));
      ph[nb][1] = h2u(__floats2half2_rn(p2, p3));
    }
    sum0 += __shfl_xor_sync(0xffffffffu, sum0, 1);
    sum0 += __shfl_xor_sync(0xffffffffu, sum0, 2);
    sum1 += __shfl_xor_sync(0xffffffffu, sum1, 1);
    sum1 += __shfl_xor_sync(0xffffffffu, sum1, 2);
    l0 = l0*al0 + sum0; l1 = l1*al1 + sum1;

    // Warp-voted rescale skip: alpha==1.0 exactly when the running max held.
    if (!__all_sync(0xffffffffu, (al0 == 1.0f) && (al1 == 1.0f))){
#pragma unroll
      for (int nb = 0; nb < 8; nb++){
        oc[nb][0] *= al0; oc[nb][1] *= al0;
        oc[nb][2] *= al1; oc[nb][3] *= al1;
      }
    }

    // ---- O += P @ V ----
#pragma unroll
    for (int ks = 0; ks < 4; ks++){
      uint32_t a[4];
      a[0] = ph[2*ks][0];   a[1] = ph[2*ks][1];
      a[2] = ph[2*ks+1][0]; a[3] = ph[2*ks+1][1];
      const uint32_t vrow = (uint32_t)(ks*16*AP*2);
#pragma unroll
      for (int nb16 = 0; nb16 < 4; nb16++){
        uint32_t vf[4];
        ldsm4t(vf, kBase + v_off + vrow + (uint32_t)(nb16*32));
        mma_f16(oc[2*nb16],   a, &vf[0]);
        mma_f16(oc[2*nb16+1], a, &vf[2]);
      }
    }
  }

  // ---- epilogue: normalize, write ctx half ----
  const int b = bh >> 4, h = bh & 15;
  const float inv0 = 1.0f / l0, inv1 = 1.0f / l1;
  __half* base0 = ctx + ((size_t)(b*SEQ + grow0)) * D_MODEL + h*HDIM;
#pragma unroll
  for (int nb = 0; nb < 8; nb++){
    const int col = 8*nb + 2*t4;
    *(__half2*)(base0 + col) = __floats2half2_rn(oc[nb][0]*inv0, oc[nb][1]*inv0);
    *(__half2*)(base0 + 8*(size_t)D_MODEL + col) = __floats2half2_rn(oc[nb][2]*inv1, oc[nb][3]*inv1);
  }
}

// ---------------------------------------------------------------------------
extern "C" void kernel_launch(void* const* d_in, const int* in_sizes, int n_in,
                              void* d_out, int out_size)
{
    const float* X  = (const float*)d_in[0];
    const float* Wq = (const float*)d_in[1];
    const float* Wk = (const float*)d_in[2];
    const float* Wv = (const float*)d_in[3];
    const float* Wo = (const float*)d_in[4];
    const float* bo = (const float*)d_in[5];
    float* out = (float*)d_out;

    __half *pq, *pk, *pv, *pctx, *phx, *phw;
    cudaGetSymbolAddress((void**)&pq,  g_q);
    cudaGetSymbolAddress((void**)&pk,  g_k);
    cudaGetSymbolAddress((void**)&pv,  g_v);
    cudaGetSymbolAddress((void**)&pctx, g_ctx);
    cudaGetSymbolAddress((void**)&phx, g_hx);
    cudaGetSymbolAddress((void**)&phw, g_hw);

    const size_t WSZ = (size_t)D_MODEL * D_MODEL;
    const __half* hWq = phw;
    const __half* hWk = phw + WSZ;
    const __half* hWv = phw + 2*WSZ;
    __half*       hWo = phw + 3*WSZ;

    // X + Wq/Wk/Wv conversion (Wo deferred into attention's tail CTAs)
    half_prep<<<592, 256>>>((const float4*)X, (const float4*)Wq, (const float4*)Wk,
                            (const float4*)Wv, (__half2*)phx, (__half2*)phw);

    cudaFuncSetAttribute(gemm_h, cudaFuncAttributeMaxDynamicSharedMemorySize, GSMEM_B);

    // QKV projections (half out; z==0 (q) pre-scaled by 1/64)
    gemm_h<<<dim3(8, 32, 3), 256, GSMEM_B>>>(phx, hWq, hWk, hWv, pq, pk, pv, nullptr, 1);

    cudaFuncSetAttribute(attn_h, cudaFuncAttributeMaxDynamicSharedMemorySize, ASMEM_B);
    // y==32 row: Wo conversion tail-riders (16 extra CTAs, launch last)
    attn_h<<<dim3(SEQ/128, BATCH*HEADS + 1), 256, ASMEM_B>>>(
        pq, pk, pv, pctx, (const float4*)Wo, (__half2*)hWo);

    // Output projection + bias (f32 out)
    gemm_h<<<dim3(8, 32, 1), 256, GSMEM_B>>>(pctx, hWo, hWo, hWo, out, out, out, bo, 0);
}

// round 17
// speedup vs baseline: 1.0488x; 1.0215x over previous
#include <cuda_runtime.h>
#include <cuda_fp16.h>
#include <math.h>
#include <stdint.h>

#define D_MODEL 1024
#define SEQ     2048
#define BATCH   2
#define HEADS   16
#define HDIM    64
#define MROWS   (BATCH*SEQ)   // 4096

// GEMM tiling (fp16): 128x128 tile, K-chunk 64, pitch 72 halves (144B).
// 3 smem stages, prefetch depth 2.
#define GP       72
#define GNIT     16
#define STG_H    (128*GP)         // halves per operand per stage (9216)
#define GSTG_B   (2*STG_H*2)      // bytes per stage (A+B) = 36864
#define GSMEM_B  (3*GSTG_B)       // 110592

// Attention: K/V tiles 64x64 fp16, pitch 72 halves. 4 stages, depth 3.
#define AP       72
#define KVH      (64*AP)          // 4608 halves per operand
#define ASTG_B   (2*KVH*2)        // bytes per stage (K+V) = 18432
#define ASMEM_B  (4*ASTG_B)       // 73728

#define LOG2E 1.44269504088896340736f

// Scratch (halves)
__device__ __half g_q[(size_t)MROWS * D_MODEL];
__device__ __half g_k[(size_t)MROWS * D_MODEL];
__device__ __half g_v[(size_t)MROWS * D_MODEL];
__device__ __half g_ctx[(size_t)MROWS * D_MODEL];
__device__ __half g_hx[(size_t)MROWS * D_MODEL];
__device__ __half g_hw[4 * (size_t)D_MODEL * D_MODEL];

// ---------------- PTX helpers ----------------
__device__ __forceinline__ uint32_t smem_u32(const void* p){
  uint32_t a;
  asm("{ .reg .u64 t; cvta.to.shared.u64 t, %1; cvt.u32.u64 %0, t; }" : "=r"(a) : "l"(p));
  return a;
}
__device__ __forceinline__ void cp_async16(uint32_t s, const void* g){
  asm volatile("cp.async.cg.shared.global [%0], [%1], 16;" :: "r"(s), "l"(g) : "memory");
}
__device__ __forceinline__ void cp_commit(){ asm volatile("cp.async.commit_group;" ::: "memory"); }
__device__ __forceinline__ void cp_wait0(){ asm volatile("cp.async.wait_group 0;" ::: "memory"); }
__device__ __forceinline__ void cp_wait1(){ asm volatile("cp.async.wait_group 1;" ::: "memory"); }
__device__ __forceinline__ void cp_wait2(){ asm volatile("cp.async.wait_group 2;" ::: "memory"); }
__device__ __forceinline__ float ex2f(float x){
  float r;
  asm("ex2.approx.f32 %0, %1;" : "=f"(r) : "f"(x));
  return r;
}
__device__ __forceinline__ void mma_f16(float* c, const uint32_t* a, const uint32_t* b){
  asm volatile(
    "mma.sync.aligned.m16n8k16.row.col.f32.f16.f16.f32 "
    "{%0,%1,%2,%3}, {%4,%5,%6,%7}, {%8,%9}, {%0,%1,%2,%3};"
    : "+f"(c[0]), "+f"(c[1]), "+f"(c[2]), "+f"(c[3])
    : "r"(a[0]), "r"(a[1]), "r"(a[2]), "r"(a[3]), "r"(b[0]), "r"(b[1]));
}
__device__ __forceinline__ void ldsm4(uint32_t* r, uint32_t addr){
  asm volatile("ldmatrix.sync.aligned.m8n8.x4.shared.b16 {%0,%1,%2,%3}, [%4];"
    : "=r"(r[0]), "=r"(r[1]), "=r"(r[2]), "=r"(r[3]) : "r"(addr));
}
__device__ __forceinline__ void ldsm4t(uint32_t* r, uint32_t addr){
  asm volatile("ldmatrix.sync.aligned.m8n8.x4.trans.shared.b16 {%0,%1,%2,%3}, [%4];"
    : "=r"(r[0]), "=r"(r[1]), "=r"(r[2]), "=r"(r[3]) : "r"(addr));
}
__device__ __forceinline__ uint32_t h2u(__half2 h){ return *(uint32_t*)&h; }

// ---------------------------------------------------------------------------
// Prep: convert X and Wq/Wk/Wv to fp16. Unrolled x4 for MLP (independent LDGs).
// ---------------------------------------------------------------------------
__global__ __launch_bounds__(256) void half_prep(
    const float4* __restrict__ X,
    const float4* __restrict__ Wq, const float4* __restrict__ Wk,
    const float4* __restrict__ Wv,
    __half2* __restrict__ hx, __half2* __restrict__ hw)
{
  const int XN = MROWS * D_MODEL / 4;
  const int WN = D_MODEL * D_MODEL / 4;
  const int total = XN + 3*WN;
  const int stride = (int)gridDim.x * 256;
  for (int i0 = blockIdx.x * 256 + threadIdx.x; i0 < total; i0 += 4*stride){
    float4 v[4];
#pragma unroll
    for (int k = 0; k < 4; k++){
      int idx = i0 + k*stride;
      if (idx < total){
        v[k] = (idx < XN) ? X[idx]
             : (idx < XN +   WN) ? Wq[idx - XN]
             : (idx < XN + 2*WN) ? Wk[idx - XN - WN]
             :                     Wv[idx - XN - 2*WN];
      }
    }
#pragma unroll
    for (int k = 0; k < 4; k++){
      int idx = i0 + k*stride;
      if (idx < total){
        __half2* dst; int j;
        if (idx < XN){ dst = hx; j = idx; }
        else {
          int w = (idx - XN) / WN;
          j = (idx - XN) - w*WN;
          dst = hw + (size_t)w * WN * 2;
        }
        dst[2*j]   = __floats2half2_rn(v[k].x, v[k].y);
        dst[2*j+1] = __floats2half2_rn(v[k].z, v[k].w);
      }
    }
  }
}

// ---------------------------------------------------------------------------
// fp16 mma GEMM, 3-stage cp.async ring (prefetch depth 2).
// mode 0: f32 out + bias. mode 1: half out; z==0 scaled by log2e/64
// (q pre-scaled into the exp2 softmax domain).
// ---------------------------------------------------------------------------
static __device__ __forceinline__ void load_stage_g(
    uint32_t stBase, const __half* A, const __half* W,
    int m0, int n0, int k0, int tid)
{
#pragma unroll
  for (int u = 0; u < 4; u++){
    int q = tid + u*256;          // 0..1023 chunks (8 halves = 16B)
    int r = q >> 3, c = q & 7;
    uint32_t so = (uint32_t)(r*GP + c*8) * 2u;
    cp_async16(stBase + so, A + (size_t)(m0 + r)*D_MODEL + k0 + c*8);
    cp_async16(stBase + (uint32_t)(STG_H*2) + so, W + (size_t)(n0 + r)*D_MODEL + k0 + c*8);
  }
}

__global__ __launch_bounds__(256) void gemm_h(
    const __half* __restrict__ A,
    const __half* __restrict__ Wa, const __half* __restrict__ Wb, const __half* __restrict__ Wc,
    void* __restrict__ Ca, void* __restrict__ Cb, void* __restrict__ Cc,
    const float* __restrict__ bias, int mode)
{
  const __half* W = (blockIdx.z == 0) ? Wa : (blockIdx.z == 1) ? Wb : Wc;
  void*         C = (blockIdx.z == 0) ? Ca : (blockIdx.z == 1) ? Cb : Cc;

  extern __shared__ __half smh[];
  const uint32_t sb = smem_u32(smh);

  const int tid  = threadIdx.x;
  const int wid  = tid >> 5;
  const int lane = tid & 31;
  const int g    = lane >> 2;
  const int t4   = lane & 3;
  const int wm   = wid >> 2;
  const int wn   = wid & 3;
  const int m0   = blockIdx.y * 128;
  const int n0   = blockIdx.x * 128;

  uint32_t a_off[4], b_off[2];
  {
    const int ra = (lane & 7) + ((lane >> 3) & 1) * 8;
    const int ka = ((lane >> 4) & 1) * 8;
    const int rb = (lane & 7) + ((lane >> 4) & 1) * 8;
    const int kb = ((lane >> 3) & 1) * 8;
#pragma unroll
    for (int mt = 0; mt < 4; mt++)
      a_off[mt] = (uint32_t)(((wm*64 + mt*16 + ra)*GP + ka) * 2);
#pragma unroll
    for (int np = 0; np < 2; np++)
      b_off[np] = (uint32_t)(((wn*32 + np*16 + rb)*GP + kb) * 2) + (uint32_t)(STG_H*2);
  }

  float c[4][4][4];
#pragma unroll
  for (int i = 0; i < 4; i++)
#pragma unroll
    for (int j = 0; j < 4; j++)
#pragma unroll
      for (int r = 0; r < 4; r++) c[i][j][r] = 0.0f;

#pragma unroll
  for (int p = 0; p < 2; p++){
    load_stage_g(sb + (uint32_t)p*GSTG_B, A, W, m0, n0, p*64, tid);
    cp_commit();
  }

  int stage = 0;
  for (int it = 0; it < GNIT; it++){
    cp_wait1();
    __syncthreads();
    if (it + 2 < GNIT){
      int sn = stage + 2; if (sn >= 3) sn -= 3;
      load_stage_g(sb + (uint32_t)sn*GSTG_B, A, W, m0, n0, (it+2)*64, tid);
    }
    cp_commit();
    const uint32_t stBase = sb + (uint32_t)stage*GSTG_B;
#pragma unroll
    for (int ks = 0; ks < 4; ks++){
      const uint32_t kbyte = (uint32_t)(ks*32);
      uint32_t af[4][4], bf[2][4];
#pragma unroll
      for (int mt = 0; mt < 4; mt++) ldsm4(af[mt], stBase + a_off[mt] + kbyte);
#pragma unroll
      for (int np = 0; np < 2; np++) ldsm4(bf[np], stBase + b_off[np] + kbyte);
#pragma unroll
      for (int mt = 0; mt < 4; mt++)
#pragma unroll
        for (int nt = 0; nt < 4; nt++)
          mma_f16(c[mt][nt], af[mt], &bf[nt >> 1][(nt & 1)*2]);
    }
    if (++stage == 3) stage = 0;
  }

  if (mode == 1){
    const float s = (blockIdx.z == 0) ? (0.015625f * LOG2E) : 1.0f;
    __half* Ch = (__half*)C;
#pragma unroll
    for (int mt = 0; mt < 4; mt++){
      const int r0 = m0 + wm*64 + mt*16 + g;
#pragma unroll
      for (int nt = 0; nt < 4; nt++){
        const int col = n0 + wn*32 + nt*8 + t4*2;
        *(__half2*)(Ch + (size_t)r0*D_MODEL + col)     = __floats2half2_rn(c[mt][nt][0]*s, c[mt][nt][1]*s);
        *(__half2*)(Ch + (size_t)(r0+8)*D_MODEL + col) = __floats2half2_rn(c[mt][nt][2]*s, c[mt][nt][3]*s);
      }
    }
  } else {
    float* Cf = (float*)C;
#pragma unroll
    for (int mt = 0; mt < 4; mt++){
      const int r0 = m0 + wm*64 + mt*16 + g;
#pragma unroll
      for (int nt = 0; nt < 4; nt++){
        const int col = n0 + wn*32 + nt*8 + t4*2;
        float b0 = bias ? bias[col] : 0.0f, b1 = bias ? bias[col+1] : 0.0f;
        *(float2*)&Cf[(size_t)r0*D_MODEL + col]     = make_float2(c[mt][nt][0]+b0, c[mt][nt][1]+b1);
        *(float2*)&Cf[(size_t)(r0+8)*D_MODEL + col] = make_float2(c[mt][nt][2]+b0, c[mt][nt][3]+b1);
      }
    }
  }
}

// ---------------------------------------------------------------------------
// fp16 mma flash attention, 4-stage K/V ring (depth 3). exp2-domain softmax
// (q pre-scaled by log2e/64; ex2.approx replaces __expf).
// Grid y: 0..31 = (b,h) attention; y==32 = Wo fp32->fp16 conversion CTAs.
// Warps 0-3 skip compute on the final k-tile (fully masked for their rows).
// Warp-voted alpha==1 skip on the oc rescale (bit-exact: x*1.0 identity).
// ---------------------------------------------------------------------------
static __device__ __forceinline__ void load_kv(
    uint32_t sb, int stage, const __half* Kt, const __half* Vt, int tid)
{
  const uint32_t base = sb + (uint32_t)stage * ASTG_B;
#pragma unroll
  for (int u = 0; u < 2; u++){
    int idx = tid + u*256;
    int r = idx >> 3, c = idx & 7;
    uint32_t so = (uint32_t)(r*AP + c*8) * 2u;
    cp_async16(base + so, Kt + (size_t)r*HDIM + c*8);
    cp_async16(base + (uint32_t)(KVH*2) + so, Vt + (size_t)r*HDIM + c*8);
  }
}

__global__ __launch_bounds__(256) void attn_h(
    const __half* __restrict__ Qg, const __half* __restrict__ Kg,
    const __half* __restrict__ Vg, __half* __restrict__ ctx,
    const float4* __restrict__ WoSrc, __half2* __restrict__ hWoDst)
{
  const int tid  = threadIdx.x;

  // Tail-rider CTAs: convert Wo to fp16 (needed only by the NEXT kernel).
  if (blockIdx.y >= BATCH*HEADS){
    const int WN = D_MODEL * D_MODEL / 4;
    for (int i = (int)blockIdx.x * 256 + tid; i < WN; i += 16*256){
      float4 v = WoSrc[i];
      hWoDst[2*i]   = __floats2half2_rn(v.x, v.y);
      hWoDst[2*i+1] = __floats2half2_rn(v.z, v.w);
    }
    return;
  }

  extern __shared__ __half smh[];
  const uint32_t sb = smem_u32(smh);

  const int wid  = tid >> 5;
  const int lane = tid & 31;
  const int g    = lane >> 2;
  const int t4   = lane & 3;
  const int bh   = blockIdx.y;
  const int qt   = (int)gridDim.x - 1 - (int)blockIdx.x;   // heavy first
  const int qbase = qt * 128;

  const __half* Qh = Qg + (size_t)bh * SEQ * HDIM;
  const __half* Kh = Kg + (size_t)bh * SEQ * HDIM;
  const __half* Vh = Vg + (size_t)bh * SEQ * HDIM;

  uint32_t q_off, k_off[4], v_off;
  {
    const int ra = (lane & 7) + ((lane >> 3) & 1) * 8;
    const int ka = ((lane >> 4) & 1) * 8;
    q_off = (uint32_t)(((wid*16 + ra)*AP + ka) * 2);
    const int rb = (lane & 7) + ((lane >> 4) & 1) * 8;
    const int kb = ((lane >> 3) & 1) * 8;
#pragma unroll
    for (int np = 0; np < 4; np++)
      k_off[np] = (uint32_t)(((np*16 + rb)*AP + kb) * 2);
    const int kr = (lane & 7) + ((lane >> 3) & 1) * 8;
    const int nc = ((lane >> 4) & 1) * 8;
    v_off = (uint32_t)((kr*AP + nc) * 2) + (uint32_t)(KVH*2);
  }

#pragma unroll
  for (int u = 0; u < 4; u++){
    int idx = tid + u*256;
    int r = idx >> 3, c = idx & 7;
    cp_async16(sb + (uint32_t)(r*AP + c*8)*2u, Qh + (size_t)(qbase + r)*HDIM + c*8);
  }
  cp_commit();
  cp_wait0();
  __syncthreads();

  uint32_t qa[4][4];
#pragma unroll
  for (int ks = 0; ks < 4; ks++) ldsm4(qa[ks], sb + q_off + (uint32_t)(ks*32));
  __syncthreads();

  float oc[8][4];
#pragma unroll
  for (int nb = 0; nb < 8; nb++)
#pragma unroll
    for (int r = 0; r < 4; r++) oc[nb][r] = 0.0f;
  float m0 = -1e30f, m1 = -1e30f, l0 = 0.0f, l1 = 0.0f;

  const int nkt = 2*qt + 2;

#pragma unroll
  for (int p = 0; p < 3; p++){
    if (p < nkt) load_kv(sb, p, Kh + (size_t)p*64*HDIM, Vh + (size_t)p*64*HDIM, tid);
    cp_commit();
  }

  const int grow0 = qbase + wid*16 + g;
  const int grow1 = grow0 + 8;

  for (int ki = 0; ki < nkt; ki++){
    cp_wait2();
    __syncthreads();
    if (ki + 3 < nkt)
      load_kv(sb, (ki+3) & 3, Kh + (size_t)(ki+3)*64*HDIM, Vh + (size_t)(ki+3)*64*HDIM, tid);
    cp_commit();

    if (ki == 2*qt + 1 && wid < 4) continue;

    const uint32_t kBase = sb + (uint32_t)(ki & 3)*ASTG_B;

    // ---- S = Q @ K^T (scores already in log2 domain via q pre-scale) ----
    float sc[8][4];
#pragma unroll
    for (int nb = 0; nb < 8; nb++)
#pragma unroll
      for (int r = 0; r < 4; r++) sc[nb][r] = 0.0f;
#pragma unroll
    for (int ks = 0; ks < 4; ks++){
      const uint32_t kbyte = (uint32_t)(ks*32);
#pragma unroll
      for (int np = 0; np < 4; np++){
        uint32_t kf[4];
        ldsm4(kf, kBase + k_off[np] + kbyte);
        mma_f16(sc[2*np],   qa[ks], &kf[0]);
        mma_f16(sc[2*np+1], qa[ks], &kf[2]);
      }
    }

    // ---- causal mask ----
    if (ki >= 2*qt){
      const int cb = ki*64 + 2*t4;
#pragma unroll
      for (int nb = 0; nb < 8; nb++){
        const int c0 = cb + 8*nb, c1 = c0 + 1;
        if (c0 > grow0) sc[nb][0] = -1e30f;
        if (c1 > grow0) sc[nb][1] = -1e30f;
        if (c0 > grow1) sc[nb][2] = -1e30f;
        if (c1 > grow1) sc[nb][3] = -1e30f;
      }
    }

    // ---- online softmax in exp2 domain (rows quad-local) ----
    float mx0 = -1e30f, mx1 = -1e30f;
#pragma unroll
    for (int nb = 0; nb < 8; nb++){
      mx0 = fmaxf(mx0, fmaxf(sc[nb][0], sc[nb][1]));
      mx1 = fmaxf(mx1, fmaxf(sc[nb][2], sc[nb][3]));
    }
    mx0 = fmaxf(mx0, __shfl_xor_sync(0xffffffffu, mx0, 1));
    mx0 = fmaxf(mx0, __shfl_xor_sync(0xffffffffu, mx0, 2));
    mx1 = fmaxf(mx1, __shfl_xor_sync(0xffffffffu, mx1, 1));
    mx1 = fmaxf(mx1, __shfl_xor_sync(0xffffffffu, mx1, 2));
    const float mn0 = fmaxf(m0, mx0), mn1 = fmaxf(m1, mx1);
    const float al0 = ex2f(m0 - mn0), al1 = ex2f(m1 - mn1);
    m0 = mn0; m1 = mn1;

    uint32_t ph[8][2];
    float sum0 = 0.0f, sum1 = 0.0f;
#pragma unroll
    for (int nb = 0; nb < 8; nb++){
      float p0 = ex2f(sc[nb][0] - mn0);
      float p1 = ex2f(sc[nb][1] - mn0);
      float p2 = ex2f(sc[nb][2] - mn1);
      float p3 = ex2f(sc[nb][3] - mn1);
      sum0 += p0 + p1; sum1 += p2 + p3;
      ph[nb][0] = h2u(__floats2half2_rn(p0, p1));
      ph[nb][1] = h2u(__floats2half2_rn(p2, p3));
    }
    sum0 += __shfl_xor_sync(0xffffffffu, sum0, 1);
    sum0 += __shfl_xor_sync(0xffffffffu, sum0, 2);
    sum1 += __shfl_xor_sync(0xffffffffu, sum1, 1);
    sum1 += __shfl_xor_sync(0xffffffffu, sum1, 2);
    l0 = l0*al0 + sum0; l1 = l1*al1 + sum1;

    // Warp-voted rescale skip: alpha==1.0 exactly when the running max held.
    if (!__all_sync(0xffffffffu, (al0 == 1.0f) && (al1 == 1.0f))){
#pragma unroll
      for (int nb = 0; nb < 8; nb++){
        oc[nb][0] *= al0; oc[nb][1] *= al0;
        oc[nb][2] *= al1; oc[nb][3] *= al1;
      }
    }

    // ---- O += P @ V ----
#pragma unroll
    for (int ks = 0; ks < 4; ks++){
      uint32_t a[4];
      a[0] = ph[2*ks][0];   a[1] = ph[2*ks][1];
      a[2] = ph[2*ks+1][0]; a[3] = ph[2*ks+1][1];
      const uint32_t vrow = (uint32_t)(ks*16*AP*2);
#pragma unroll
      for (int nb16 = 0; nb16 < 4; nb16++){
        uint32_t vf[4];
        ldsm4t(vf, kBase + v_off + vrow + (uint32_t)(nb16*32));
        mma_f16(oc[2*nb16],   a, &vf[0]);
        mma_f16(oc[2*nb16+1], a, &vf[2]);
      }
    }
  }

  // ---- epilogue: normalize, write ctx half ----
  const int b = bh >> 4, h = bh & 15;
  const float inv0 = 1.0f / l0, inv1 = 1.0f / l1;
  __half* base0 = ctx + ((size_t)(b*SEQ + grow0)) * D_MODEL + h*HDIM;
#pragma unroll
  for (int nb = 0; nb < 8; nb++){
    const int col = 8*nb + 2*t4;
    *(__half2*)(base0 + col) = __floats2half2_rn(oc[nb][0]*inv0, oc[nb][1]*inv0);
    *(__half2*)(base0 + 8*(size_t)D_MODEL + col) = __floats2half2_rn(oc[nb][2]*inv1, oc[nb][3]*inv1);
  }
}

// ---------------------------------------------------------------------------
extern "C" void kernel_launch(void* const* d_in, const int* in_sizes, int n_in,
                              void* d_out, int out_size)
{
    const float* X  = (const float*)d_in[0];
    const float* Wq = (const float*)d_in[1];
    const float* Wk = (const float*)d_in[2];
    const float* Wv = (const float*)d_in[3];
    const float* Wo = (const float*)d_in[4];
    const float* bo = (const float*)d_in[5];
    float* out = (float*)d_out;

    __half *pq, *pk, *pv, *pctx, *phx, *phw;
    cudaGetSymbolAddress((void**)&pq,  g_q);
    cudaGetSymbolAddress((void**)&pk,  g_k);
    cudaGetSymbolAddress((void**)&pv,  g_v);
    cudaGetSymbolAddress((void**)&pctx, g_ctx);
    cudaGetSymbolAddress((void**)&phx, g_hx);
    cudaGetSymbolAddress((void**)&phw, g_hw);

    const size_t WSZ = (size_t)D_MODEL * D_MODEL;
    const __half* hWq = phw;
    const __half* hWk = phw + WSZ;
    const __half* hWv = phw + 2*WSZ;
    __half*       hWo = phw + 3*WSZ;

    // X + Wq/Wk/Wv conversion (Wo deferred into attention's tail CTAs)
    half_prep<<<592, 256>>>((const float4*)X, (const float4*)Wq, (const float4*)Wk,
                            (const float4*)Wv, (__half2*)phx, (__half2*)phw);

    cudaFuncSetAttribute(gemm_h, cudaFuncAttributeMaxDynamicSharedMemorySize, GSMEM_B);

    // QKV projections (half out; z==0 (q) pre-scaled by log2e/64)
    gemm_h<<<dim3(8, 32, 3), 256, GSMEM_B>>>(phx, hWq, hWk, hWv, pq, pk, pv, nullptr, 1);

    cudaFuncSetAttribute(attn_h, cudaFuncAttributeMaxDynamicSharedMemorySize, ASMEM_B);
    // y==32 row: Wo conversion tail-riders (16 extra CTAs, launch last)
    attn_h<<<dim3(SEQ/128, BATCH*HEADS + 1), 256, ASMEM_B>>>(
        pq, pk, pv, pctx, (const float4*)Wo, (__half2*)hWo);

    // Output projection + bias (f32 out)
    gemm_h<<<dim3(8, 32, 1), 256, GSMEM_B>>>(pctx, hWo, hWo, hWo, out, out, out, bo, 0);
}